// round 1
// baseline (speedup 1.0000x reference)
#include <cuda_runtime.h>
#include <cuda_bf16.h>

#define NN 100000
#define EE 1600000
#define GG 64

// ---------------- device scratch (static: no allocation allowed) ----------------
__device__ float g_h1[NN * 16];
__device__ float g_h2[NN * 32];
__device__ float g_h3[NN * 64];
__device__ float g_h4[NN * 128];
__device__ float g_agg[NN * 64];     // max Fin = 64
__device__ float g_dinv[NN];
__device__ int   g_deg[NN];
__device__ float g_norm[EE];
__device__ float g_psum[GG * 128];
__device__ int   g_pcnt[GG];

// vector reduction (no return) to global fp32 — sm_90+
__device__ __forceinline__ void red_add_v4(float* p, float4 v) {
    asm volatile("red.global.add.v4.f32 [%0], {%1,%2,%3,%4};"
                 :: "l"(p), "f"(v.x), "f"(v.y), "f"(v.z), "f"(v.w)
                 : "memory");
}

// ---------------- degree / normalization ----------------
__global__ void k_deg_init() {
    int n = blockIdx.x * blockDim.x + threadIdx.x;
    if (n < NN) g_deg[n] = 1;   // self loop
}
__global__ void k_deg_count(const int* __restrict__ dst) {
    int e = blockIdx.x * blockDim.x + threadIdx.x;
    if (e < EE) atomicAdd(&g_deg[dst[e]], 1);
}
__global__ void k_dinv() {
    int n = blockIdx.x * blockDim.x + threadIdx.x;
    if (n < NN) g_dinv[n] = rsqrtf((float)g_deg[n]);
}
__global__ void k_norm(const int* __restrict__ src, const int* __restrict__ dst) {
    int e = blockIdx.x * blockDim.x + threadIdx.x;
    if (e < EE) g_norm[e] = g_dinv[src[e]] * g_dinv[dst[e]];
}

// map Fin -> input feature pointer (layer1 uses x passed from host)
template<int F>
__device__ __forceinline__ const float* layer_in(const float* x) {
    if constexpr (F == 8)  return x;
    else if constexpr (F == 16) return g_h1;
    else if constexpr (F == 32) return g_h2;
    else                        return g_h3;
}
template<int FOUT>
__device__ __forceinline__ float* layer_out() {
    if constexpr (FOUT == 16)  return g_h1;
    else if constexpr (FOUT == 32)  return g_h2;
    else if constexpr (FOUT == 64)  return g_h3;
    else                            return g_h4;
}

// ---------------- aggregation: agg = Dinv A_hat Dinv * h  (Fin features) -----
// self-loop term (also zero-initializes agg)
template<int F>
__global__ void k_selfinit(const float* __restrict__ x) {
    const float* __restrict__ h = layer_in<F>(x);
    unsigned t = blockIdx.x * blockDim.x + threadIdx.x;   // over NN*F/4
    if (t >= (unsigned)(NN * (F / 4))) return;
    unsigned n = t / (F / 4);
    float d = g_dinv[n];
    float s = d * d;
    float4 v = reinterpret_cast<const float4*>(h)[t];
    float4 r = make_float4(v.x * s, v.y * s, v.z * s, v.w * s);
    reinterpret_cast<float4*>(g_agg)[t] = r;
}

// edge scatter: one thread per (edge, float4-chunk)
template<int F>
__global__ void k_edge(const int* __restrict__ src, const int* __restrict__ dst,
                       const float* __restrict__ x) {
    constexpr int C = F / 4;
    const float* __restrict__ h = layer_in<F>(x);
    unsigned t = blockIdx.x * blockDim.x + threadIdx.x;
    if (t >= (unsigned)EE * C) return;
    unsigned e = t / C;
    unsigned c = t % C;
    int s = __ldg(src + e);
    int d = __ldg(dst + e);
    float nm = __ldg(g_norm + e);
    float4 v = __ldg(reinterpret_cast<const float4*>(h + (size_t)s * F) + c);
    float4 r = make_float4(v.x * nm, v.y * nm, v.z * nm, v.w * nm);
    red_add_v4(g_agg + (size_t)d * F + 4 * c, r);
}

// ---------------- dense transform: h_out = prelu(agg @ W + b) ----------------
// warp per node, W staged in shared
template<int FIN, int FOUT, bool PRELU>
__global__ void k_transform(const float* __restrict__ W, const float* __restrict__ b,
                            const float* __restrict__ aP) {
    __shared__ float Ws[FIN * FOUT];
    __shared__ float bs[FOUT];
    for (int i = threadIdx.x; i < FIN * FOUT; i += blockDim.x) Ws[i] = W[i];
    for (int i = threadIdx.x; i < FOUT; i += blockDim.x) bs[i] = b[i];
    __syncthreads();
    float a = 0.0f;
    if constexpr (PRELU) a = aP[0];

    int warp = threadIdx.x >> 5;
    int lane = threadIdx.x & 31;
    int node = blockIdx.x * (blockDim.x >> 5) + warp;
    if (node >= NN) return;

    constexpr int OPL = (FOUT + 31) / 32;
    float acc[OPL];
#pragma unroll
    for (int j = 0; j < OPL; j++) {
        int o = lane + 32 * j;
        acc[j] = (o < FOUT) ? bs[o] : 0.0f;
    }
    const float* __restrict__ hrow = g_agg + (size_t)node * FIN;
#pragma unroll
    for (int k4 = 0; k4 < FIN; k4 += 4) {
        float4 h4 = __ldg(reinterpret_cast<const float4*>(hrow + k4));
        float hv[4] = {h4.x, h4.y, h4.z, h4.w};
#pragma unroll
        for (int kk = 0; kk < 4; kk++) {
            float hk = hv[kk];
#pragma unroll
            for (int j = 0; j < OPL; j++) {
                int o = lane + 32 * j;
                if (o < FOUT) acc[j] += hk * Ws[(k4 + kk) * FOUT + o];
            }
        }
    }
    float* __restrict__ out = layer_out<FOUT>();
#pragma unroll
    for (int j = 0; j < OPL; j++) {
        int o = lane + 32 * j;
        if (o < FOUT) {
            float v = acc[j];
            if constexpr (PRELU) v = (v >= 0.0f) ? v : a * v;
            out[(size_t)node * FOUT + o] = v;
        }
    }
}

// ---------------- pooling + head ----------------
__global__ void k_pool_zero() {
    int t = blockIdx.x * blockDim.x + threadIdx.x;
    if (t < GG * 128) g_psum[t] = 0.0f;
    if (t < GG) g_pcnt[t] = 0;
}
__global__ void k_pool(const int* __restrict__ batch) {
    unsigned t = blockIdx.x * blockDim.x + threadIdx.x;  // NN * 32 chunks
    if (t >= (unsigned)NN * 32) return;
    unsigned n = t >> 5;
    unsigned c = t & 31;
    int b = __ldg(batch + n);
    float4 v = reinterpret_cast<const float4*>(g_h4)[t];
    red_add_v4(&g_psum[b * 128 + c * 4], v);
    if (c == 0) atomicAdd(&g_pcnt[b], 1);
}
__global__ void k_final(const float* __restrict__ Wlin, const float* __restrict__ blin,
                        float* __restrict__ out) {
    int t = threadIdx.x;            // 256 = 64 graphs x 4 classes
    int g = t >> 2;
    int cls = t & 3;
    float inv = 1.0f / fmaxf((float)g_pcnt[g], 1.0f);
    float acc = blin[cls];
#pragma unroll 8
    for (int k = 0; k < 128; k++)
        acc += g_psum[g * 128 + k] * inv * Wlin[k * 4 + cls];
    out[g * 4 + cls] = acc;
}

// ---------------- launch ----------------
extern "C" void kernel_launch(void* const* d_in, const int* in_sizes, int n_in,
                              void* d_out, int out_size) {
    const float* x    = (const float*)d_in[0];
    const int*   es   = (const int*)d_in[1];
    const int*   ed   = (const int*)d_in[2];
    const int*   bt   = (const int*)d_in[3];
    const float* W1   = (const float*)d_in[4];
    const float* b1   = (const float*)d_in[5];
    const float* W2   = (const float*)d_in[6];
    const float* b2   = (const float*)d_in[7];
    const float* W3   = (const float*)d_in[8];
    const float* b3   = (const float*)d_in[9];
    const float* W4   = (const float*)d_in[10];
    const float* b4   = (const float*)d_in[11];
    const float* a1   = (const float*)d_in[12];
    const float* a2   = (const float*)d_in[13];
    const float* a3   = (const float*)d_in[14];
    const float* Wlin = (const float*)d_in[15];
    const float* blin = (const float*)d_in[16];

    const int B = 256;
    auto gr = [](long long n, int b) { return (unsigned)((n + b - 1) / b); };

    // degree + normalization
    k_deg_init<<<gr(NN, B), B>>>();
    k_deg_count<<<gr(EE, B), B>>>(ed);
    k_dinv<<<gr(NN, B), B>>>();
    k_norm<<<gr(EE, B), B>>>(es, ed);

    // layer 1: agg x (Fin=8) -> W1 (8x16) + prelu
    k_selfinit<8><<<gr((long long)NN * 2, B), B>>>(x);
    k_edge<8><<<gr((long long)EE * 2, B), B>>>(es, ed, x);
    k_transform<8, 16, true><<<gr(NN, 8), B>>>(W1, b1, a1);

    // layer 2: 16 -> 32
    k_selfinit<16><<<gr((long long)NN * 4, B), B>>>(x);
    k_edge<16><<<gr((long long)EE * 4, B), B>>>(es, ed, x);
    k_transform<16, 32, true><<<gr(NN, 8), B>>>(W2, b2, a2);

    // layer 3: 32 -> 64
    k_selfinit<32><<<gr((long long)NN * 8, B), B>>>(x);
    k_edge<32><<<gr((long long)EE * 8, B), B>>>(es, ed, x);
    k_transform<32, 64, true><<<gr(NN, 8), B>>>(W3, b3, a3);

    // layer 4: 64 -> 128, no prelu
    k_selfinit<64><<<gr((long long)NN * 16, B), B>>>(x);
    k_edge<64><<<gr((long long)EE * 16, B), B>>>(es, ed, x);
    k_transform<64, 128, false><<<gr(NN, 8), B>>>(W4, b4, a3);

    // mean pool + linear head
    k_pool_zero<<<gr(GG * 128, B), B>>>();
    k_pool<<<gr((long long)NN * 32, B), B>>>(bt);
    k_final<<<1, 256>>>(Wlin, blin, (float*)d_out);
}

// round 2
// speedup vs baseline: 1.2511x; 1.2511x over previous
#include <cuda_runtime.h>
#include <cuda_bf16.h>

#define NN 100000
#define EE 1600000
#define GG 64
#define NB ((NN + 255) / 256)   // 391 scan blocks

// ---------------- device scratch (static: no allocation allowed) ----------------
__device__ float g_hp0[NN * 8];
__device__ float g_hp1[NN * 16];
__device__ float g_hp2[NN * 32];
__device__ float g_hp3[NN * 64];
__device__ int   g_csr[EE];
__device__ int   g_rowptr[NN];
__device__ int   g_cnt[NN];
__device__ int   g_deg[NN];        // in-degree WITHOUT self loop
__device__ float g_dinv[NN];
__device__ int   g_bsum[NB];
__device__ float g_psum[GG * 128];
__device__ int   g_pcnt[GG];

__device__ __forceinline__ void red_add_v4(float* p, float4 v) {
    asm volatile("red.global.add.v4.f32 [%0], {%1,%2,%3,%4};"
                 :: "l"(p), "f"(v.x), "f"(v.y), "f"(v.z), "f"(v.w)
                 : "memory");
}

// ---------------- init / degree ----------------
__global__ void k_zero() {
    int i = blockIdx.x * blockDim.x + threadIdx.x;
    if (i < NN) g_deg[i] = 0;
    if (i < GG * 128) g_psum[i] = 0.0f;
    if (i < GG) g_pcnt[i] = 0;
}
__global__ void k_deg_count(const int* __restrict__ dst) {
    int e = blockIdx.x * blockDim.x + threadIdx.x;
    if (e < EE) atomicAdd(&g_deg[dst[e]], 1);
}
__global__ void k_dinv(const int* __restrict__ batch) {
    int n = blockIdx.x * blockDim.x + threadIdx.x;
    if (n < NN) {
        g_dinv[n] = rsqrtf((float)(g_deg[n] + 1));
        atomicAdd(&g_pcnt[batch[n]], 1);
    }
}

// ---------------- exclusive scan of g_deg -> g_rowptr ----------------
__global__ void k_scan1() {
    int t = threadIdx.x;
    int i = blockIdx.x * 256 + t;
    int v = (i < NN) ? g_deg[i] : 0;
    int lane = t & 31, w = t >> 5;
    int x = v;
#pragma unroll
    for (int d = 1; d < 32; d <<= 1) {
        int y = __shfl_up_sync(0xffffffffu, x, d);
        if (lane >= d) x += y;
    }
    __shared__ int ws[8];
    if (lane == 31) ws[w] = x;
    __syncthreads();
    if (w == 0) {
        int y = (lane < 8) ? ws[lane] : 0;
#pragma unroll
        for (int d = 1; d < 8; d <<= 1) {
            int z = __shfl_up_sync(0xffffffffu, y, d);
            if (lane >= d) y += z;
        }
        if (lane < 8) ws[lane] = y;
    }
    __syncthreads();
    int base = (w > 0) ? ws[w - 1] : 0;
    int incl = base + x;
    if (i < NN) g_rowptr[i] = incl - v;
    if (t == 255) g_bsum[blockIdx.x] = incl;
}
__global__ void k_scan2() {
    int t = threadIdx.x;                       // 512 threads
    int v = (t < NB) ? g_bsum[t] : 0;
    int lane = t & 31, w = t >> 5;
    int x = v;
#pragma unroll
    for (int d = 1; d < 32; d <<= 1) {
        int y = __shfl_up_sync(0xffffffffu, x, d);
        if (lane >= d) x += y;
    }
    __shared__ int ws[16];
    if (lane == 31) ws[w] = x;
    __syncthreads();
    if (w == 0) {
        int y = (lane < 16) ? ws[lane] : 0;
#pragma unroll
        for (int d = 1; d < 16; d <<= 1) {
            int z = __shfl_up_sync(0xffffffffu, y, d);
            if (lane >= d) y += z;
        }
        if (lane < 16) ws[lane] = y;
    }
    __syncthreads();
    int base = (w > 0) ? ws[w - 1] : 0;
    if (t < NB) g_bsum[t] = base + x - v;
}
__global__ void k_scan3() {
    int i = blockIdx.x * blockDim.x + threadIdx.x;
    if (i < NN) {
        int r = g_rowptr[i] + g_bsum[i >> 8];
        g_rowptr[i] = r;
        g_cnt[i] = r;
    }
}
__global__ void k_fill(const int* __restrict__ src, const int* __restrict__ dst) {
    int e = blockIdx.x * blockDim.x + threadIdx.x;
    if (e < EE) {
        int pos = atomicAdd(&g_cnt[dst[e]], 1);
        g_csr[pos] = src[e];
    }
}

// ---------------- prescale layer-1 input ----------------
__global__ void k_prep(const float* __restrict__ x) {
    unsigned t = blockIdx.x * blockDim.x + threadIdx.x;
    if (t >= (unsigned)NN * 2) return;
    unsigned n = t >> 1;
    float d = g_dinv[n];
    float4 v = reinterpret_cast<const float4*>(x)[t];
    reinterpret_cast<float4*>(g_hp0)[t] =
        make_float4(v.x * d, v.y * d, v.z * d, v.w * d);
}

// ---------------- fused layer ----------------
__device__ __forceinline__ const float* hp_in_of(int layer) {
    switch (layer) { case 1: return g_hp0; case 2: return g_hp1;
                     case 3: return g_hp2; default: return g_hp3; }
}
__device__ __forceinline__ float* hp_out_of(int layer) {
    switch (layer) { case 1: return g_hp1; case 2: return g_hp2;
                     default: return g_hp3; }
}

template<int LYR, int FIN, int FOUT, bool PRELU, bool FINAL>
__global__ void __launch_bounds__(256)
k_layer(const float* __restrict__ W, const float* __restrict__ b,
        const float* __restrict__ aP, const int* __restrict__ batch)
{
    constexpr int L = FIN / 2;            // lanes per node
    constexpr int NPW = 32 / L;           // nodes per warp
    static_assert(FOUT == 4 * L, "mapping assumes FOUT = 2*FIN");
    __shared__ alignas(16) float Ws[FIN * FOUT];
    __shared__ float bs[FOUT];
    for (int i = threadIdx.x; i < FIN * FOUT; i += blockDim.x) Ws[i] = W[i];
    for (int i = threadIdx.x; i < FOUT; i += blockDim.x) bs[i] = b[i];
    __syncthreads();
    float a = 0.0f;
    if constexpr (PRELU) a = __ldg(aP);

    const float* hp_in = hp_in_of(LYR);

    int warp = threadIdx.x >> 5, lane = threadIdx.x & 31;
    int sub = lane % L;
    int node = (blockIdx.x * 8 + warp) * NPW + lane / L;
    if (node >= NN) return;

    const float2* __restrict__ hp2 = reinterpret_cast<const float2*>(hp_in);
    float2 acc = __ldg(&hp2[(size_t)node * L + sub]);          // self loop
    int e = __ldg(&g_rowptr[node]);
    int rem = __ldg(&g_deg[node]);
    for (; rem >= 4; rem -= 4, e += 4) {
        int s0 = __ldg(g_csr + e), s1 = __ldg(g_csr + e + 1);
        int s2 = __ldg(g_csr + e + 2), s3 = __ldg(g_csr + e + 3);
        float2 v0 = __ldg(&hp2[(size_t)s0 * L + sub]);
        float2 v1 = __ldg(&hp2[(size_t)s1 * L + sub]);
        float2 v2 = __ldg(&hp2[(size_t)s2 * L + sub]);
        float2 v3 = __ldg(&hp2[(size_t)s3 * L + sub]);
        acc.x += (v0.x + v1.x) + (v2.x + v3.x);
        acc.y += (v0.y + v1.y) + (v2.y + v3.y);
    }
    for (; rem > 0; rem--, e++) {
        int s = __ldg(g_csr + e);
        float2 v = __ldg(&hp2[(size_t)s * L + sub]);
        acc.x += v.x; acc.y += v.y;
    }
    float dv = __ldg(&g_dinv[node]);
    acc.x *= dv; acc.y *= dv;

    float r0 = bs[4 * sub], r1 = bs[4 * sub + 1];
    float r2 = bs[4 * sub + 2], r3 = bs[4 * sub + 3];
#pragma unroll
    for (int k2 = 0; k2 < L; k2++) {
        float hx = __shfl_sync(0xffffffffu, acc.x, k2, L);
        float hy = __shfl_sync(0xffffffffu, acc.y, k2, L);
        float4 wa = *reinterpret_cast<const float4*>(&Ws[(2 * k2) * FOUT + 4 * sub]);
        float4 wb = *reinterpret_cast<const float4*>(&Ws[(2 * k2 + 1) * FOUT + 4 * sub]);
        r0 += hx * wa.x + hy * wb.x;
        r1 += hx * wa.y + hy * wb.y;
        r2 += hx * wa.z + hy * wb.z;
        r3 += hx * wa.w + hy * wb.w;
    }
    if constexpr (PRELU) {
        r0 = (r0 >= 0.f) ? r0 : a * r0;
        r1 = (r1 >= 0.f) ? r1 : a * r1;
        r2 = (r2 >= 0.f) ? r2 : a * r2;
        r3 = (r3 >= 0.f) ? r3 : a * r3;
    }
    if constexpr (FINAL) {
        int g = __ldg(&batch[node]);
        red_add_v4(&g_psum[g * 128 + 4 * sub], make_float4(r0, r1, r2, r3));
    } else {
        float* hp_out = hp_out_of(LYR);
        float4 r = make_float4(r0 * dv, r1 * dv, r2 * dv, r3 * dv);
        reinterpret_cast<float4*>(hp_out)[(size_t)node * L + sub] = r;
    }
}

// ---------------- head ----------------
__global__ void k_final(const float* __restrict__ Wlin, const float* __restrict__ blin,
                        float* __restrict__ out) {
    int t = threadIdx.x;            // 64 graphs x 4 classes
    int g = t >> 2;
    int cls = t & 3;
    float inv = 1.0f / fmaxf((float)g_pcnt[g], 1.0f);
    float acc = blin[cls];
#pragma unroll 8
    for (int k = 0; k < 128; k++)
        acc += g_psum[g * 128 + k] * inv * Wlin[k * 4 + cls];
    out[g * 4 + cls] = acc;
}

// ---------------- launch ----------------
extern "C" void kernel_launch(void* const* d_in, const int* in_sizes, int n_in,
                              void* d_out, int out_size) {
    const float* x    = (const float*)d_in[0];
    const int*   es   = (const int*)d_in[1];
    const int*   ed   = (const int*)d_in[2];
    const int*   bt   = (const int*)d_in[3];
    const float* W1   = (const float*)d_in[4];
    const float* b1   = (const float*)d_in[5];
    const float* W2   = (const float*)d_in[6];
    const float* b2   = (const float*)d_in[7];
    const float* W3   = (const float*)d_in[8];
    const float* b3   = (const float*)d_in[9];
    const float* W4   = (const float*)d_in[10];
    const float* b4   = (const float*)d_in[11];
    const float* a1   = (const float*)d_in[12];
    const float* a2   = (const float*)d_in[13];
    const float* a3   = (const float*)d_in[14];
    const float* Wlin = (const float*)d_in[15];
    const float* blin = (const float*)d_in[16];

    const int B = 256;
    auto gr = [](long long n, int b) { return (unsigned)((n + b - 1) / b); };

    k_zero<<<gr(NN, B), B>>>();
    k_deg_count<<<gr(EE, B), B>>>(ed);
    k_dinv<<<gr(NN, B), B>>>(bt);
    k_scan1<<<NB, 256>>>();
    k_scan2<<<1, 512>>>();
    k_scan3<<<gr(NN, B), B>>>();
    k_fill<<<gr(EE, B), B>>>(es, ed);
    k_prep<<<gr((long long)NN * 2, B), B>>>(x);

    // fused layers: nodes/block = 8 warps * (32 / (FIN/2))
    k_layer<1, 8, 16, true, false><<<gr(NN, 64), B>>>(W1, b1, a1, nullptr);
    k_layer<2, 16, 32, true, false><<<gr(NN, 32), B>>>(W2, b2, a2, nullptr);
    k_layer<3, 32, 64, true, false><<<gr(NN, 16), B>>>(W3, b3, a3, nullptr);
    k_layer<4, 64, 128, false, true><<<gr(NN, 8), B>>>(W4, b4, nullptr, bt);

    k_final<<<1, 256>>>(Wlin, blin, (float*)d_out);
}